// round 12
// baseline (speedup 1.0000x reference)
#include <cuda_runtime.h>
#include <cuda_bf16.h>

// EmbeddedGCN: out[b,i,o] = relu( sum_j adj[b,i,j] * (concat(s1,s2)[b,i,j,:] @ W)[o] + bias[o] )
// Linearity rewrite:
//   y[b,i,f]   = sum_j adj[b,i,j] * concat(s1,s2)[b,i,j,f]     (gated gather-reduce)
//   out[b,i,o] = relu( sum_f y[f]*W[f,o] + bias[o]*rowsum(adj) )
//
// B=16, M=128, FE=64 (concat -> 128), FO=128.
// R3 skeleton (best so far): 256 threads, 8 warps, one warp per row, RPB=8,
// grid 256. Change vs R3: gather uses a two-deep pipeline of 8-wide batches
// (effective MLP-16) -> dependent DRAM rounds per row drop from 4 to ~2.

#define BM 128
#define FE 64
#define FT 128
#define FO 128
#define RPB 8     // rows per block

__global__ __launch_bounds__(256, 2)
void gcn_fused5(const float* __restrict__ s1,
                const float* __restrict__ s2,
                const float* __restrict__ adj,
                const float* __restrict__ W,
                const float* __restrict__ bias,
                float* __restrict__ out)
{
    __shared__ int   jidx_s[RPB][BM];
    __shared__ float aval_s[RPB][BM];
    __shared__ float y_s[RPB][FT];
    __shared__ float rowsum_s[RPB];

    const int tid  = threadIdx.x;     // 0..255
    const int lane = tid & 31;
    const int w    = tid >> 5;        // warp id = local row id, 0..7
    const int bi0  = blockIdx.x * RPB;
    const int row  = bi0 + w;         // flat b*M + i

    // ---- Phase 1a: adjacency load + warp-prefix compaction ----
    const float4 av = *(const float4*)(adj + (size_t)row * BM + lane * 4);
    int   cnt  = 0;
    float rsum = 0.0f;
    {
        const unsigned lt = (1u << lane) - 1u;
        #pragma unroll
        for (int q = 0; q < 4; q++) {
            const float a = (q == 0) ? av.x : (q == 1) ? av.y : (q == 2) ? av.z : av.w;
            const unsigned m = __ballot_sync(0xFFFFFFFFu, a != 0.0f);
            if (a != 0.0f) {
                const int pos = cnt + __popc(m & lt);
                jidx_s[w][pos] = lane * 4 + q;
                aval_s[w][pos] = a;
            }
            cnt  += __popc(m);
            rsum += a;
        }
        #pragma unroll
        for (int off = 16; off > 0; off >>= 1)
            rsum += __shfl_xor_sync(0xFFFFFFFFu, rsum, off);
        if (lane == 0) rowsum_s[w] = rsum;
    }
    __syncwarp();

    // ---- Phase 1b: gather-reduce, two-deep pipeline of 8-wide batches ----
    // lane -> one float4 of the 128-wide concat row:
    //   lanes 0..15  -> s1, float4 idx = lane        (features 0..63)
    //   lanes 16..31 -> s2, float4 idx = lane - 16   (features 64..127)
    const float4* base4;
    {
        const size_t row0 = (size_t)row * (size_t)(BM * FE);
        base4 = (lane < 16) ? ((const float4*)(s1 + row0) + lane)
                            : ((const float4*)(s2 + row0) + (lane - 16));
    }
    const int jsafe = jidx_s[w][0];   // dummy target for invalid slots (L1 hit)

    float4 v0[8], v1[8];

    // issue batch starting at slot k0 into buf (predicated by cnt)
    #define ISSUE(buf, k0)                                              \
        {                                                               \
            _Pragma("unroll")                                           \
            for (int t = 0; t < 8; t++) {                               \
                const int  kk = (k0) + t;                               \
                const int  j  = (kk < cnt) ? jidx_s[w][kk] : jsafe;     \
                buf[t] = __ldg(base4 + (size_t)j * 16);                 \
            }                                                           \
        }

    // consume batch starting at slot k0 from buf (a=0 for invalid slots)
    #define CONSUME(buf, k0)                                            \
        {                                                               \
            _Pragma("unroll")                                           \
            for (int t = 0; t < 8; t++) {                               \
                const int   kk = (k0) + t;                              \
                const float a  = (kk < cnt) ? aval_s[w][kk] : 0.0f;     \
                acc.x = fmaf(a, buf[t].x, acc.x);                       \
                acc.y = fmaf(a, buf[t].y, acc.y);                       \
                acc.z = fmaf(a, buf[t].z, acc.z);                       \
                acc.w = fmaf(a, buf[t].w, acc.w);                       \
            }                                                           \
        }

    float4 acc = make_float4(0.f, 0.f, 0.f, 0.f);

    ISSUE(v0, 0)
    ISSUE(v1, 8)
    for (int k0 = 0; k0 < cnt; k0 += 16) {
        CONSUME(v0, k0)
        ISSUE(v0, k0 + 16)
        CONSUME(v1, k0 + 8)
        ISSUE(v1, k0 + 24)
    }
    #undef ISSUE
    #undef CONSUME

    {
        const int fb = (lane < 16) ? (lane * 4) : (FE + (lane - 16) * 4);
        *(float4*)&y_s[w][fb] = acc;
    }
    __syncthreads();

    // ---- Phase 2: out[r,o] = relu( y[r,:] @ W[:,o] + bias[o]*rowsum[r] ) ----
    // 256 threads: o = tid&127, group g = tid>>7 owns 4 rows (W reuse x8/block).
    const int o  = tid & (FO - 1);
    const int g  = tid >> 7;          // 0 or 1
    const int r0 = g * 4;

    float accO[4];
    {
        const float bo = __ldg(bias + o);
        #pragma unroll
        for (int q = 0; q < 4; q++) accO[q] = bo * rowsum_s[r0 + q];
    }

    #pragma unroll 8
    for (int f = 0; f < FT; f += 4) {
        const float w0 = __ldg(W + (f + 0) * FO + o);
        const float w1 = __ldg(W + (f + 1) * FO + o);
        const float w2 = __ldg(W + (f + 2) * FO + o);
        const float w3 = __ldg(W + (f + 3) * FO + o);
        #pragma unroll
        for (int q = 0; q < 4; q++) {
            const float4 y = *(const float4*)&y_s[r0 + q][f];
            accO[q] = fmaf(y.x, w0, accO[q]);
            accO[q] = fmaf(y.y, w1, accO[q]);
            accO[q] = fmaf(y.z, w2, accO[q]);
            accO[q] = fmaf(y.w, w3, accO[q]);
        }
    }

    #pragma unroll
    for (int q = 0; q < 4; q++)
        out[(size_t)(bi0 + r0 + q) * FO + o] = fmaxf(accO[q], 0.0f);
}

extern "C" void kernel_launch(void* const* d_in, const int* in_sizes, int n_in,
                              void* d_out, int out_size)
{
    const float* s1   = (const float*)d_in[0];  // (16,128,128,64)
    const float* s2   = (const float*)d_in[1];  // (16,128,128,64)
    const float* adj  = (const float*)d_in[2];  // (16,128,128)
    const float* W    = (const float*)d_in[3];  // (128,128)
    const float* bias = (const float*)d_in[4];  // (128,)
    float* out = (float*)d_out;                 // (16,128,128)

    gcn_fused5<<<(16 * 128) / RPB, 256>>>(s1, s2, adj, W, bias, out);
}